// round 11
// baseline (speedup 1.0000x reference)
#include <cuda_runtime.h>
#include <stdint.h>

// LengthRegulator, fused single-launch.
//   out[n, t, :] = x[n, searchsorted(csum[n], t, 'right'), :] for t < total[n], else 0
//   mel_pos = [1..T] appended after the frames.
//
// Output layout (validated via out_size divisibility, N*C = 24576):
//   case A: [ out: N*T*C f32 ][ mel_pos: T f32 ]
//   case B: [ out: N*T*C f32 ][ mel_pos: T i64 ]
//
// R11 = R10 copy-loop shape (regs 26, kernel 41.4us) with FRAMES 24 -> 48:
//   grid 6336 -> ~3200 blocks (~3 waves). Evidence: bench-kernel gap scales
//   with block count (1024 blocks -> 1.4us gap, 6336 -> 4.2us), while many
//   blocks self-balance better than one wave. 48 frames/block amortizes the
//   scan prologue over 72KB of writes and halves total dispatch.

#define L_LEN    256
#define THREADS  288           // 3 frame-groups x 96 channel chunks
#define FRAMES   48
#define FPG      16            // frames walked per thread (2 batches of 8)

__global__ __launch_bounds__(THREADS)
void lr_fused_kernel(const float* __restrict__ x,
                     const int* __restrict__ dur,
                     float* __restrict__ out,
                     float* __restrict__ mp,
                     int T, int mel_is_i64)
{
    const int n    = blockIdx.y;
    const int t0   = blockIdx.x * FRAMES;
    const int tid  = threadIdx.x;
    const int wid  = tid >> 5;
    const int lane = tid & 31;

    __shared__ int csum[L_LEN];
    __shared__ int wsum[8];
    __shared__ int fidx[FRAMES];

    // ---- mel_pos: row-0 blocks write their 48 entries ----
    if (blockIdx.y == 0 && tid < FRAMES) {
        int t = t0 + tid;
        if (t < T) {
            if (mel_is_i64) ((long long*)mp)[t] = (long long)(t + 1);
            else            mp[t] = (float)(t + 1);
        }
    }

    // ---- inclusive prefix sum of durations (shuffle scan, warps 0..7) ----
    int v = 0;
    if (tid < L_LEN) {
        v = dur[n * L_LEN + tid];
        #pragma unroll
        for (int off = 1; off < 32; off <<= 1) {
            int u = __shfl_up_sync(0xFFFFFFFFu, v, off);
            if (lane >= off) v += u;
        }
        if (lane == 31) wsum[wid] = v;
    }
    __syncthreads();
    if (wid == 0 && lane < 8) {
        int s = wsum[lane];
        #pragma unroll
        for (int off = 1; off < 8; off <<= 1) {
            int u = __shfl_up_sync(0xFFu, s, off);
            if (lane >= off) s += u;
        }
        wsum[lane] = s;
    }
    __syncthreads();
    if (tid < L_LEN) csum[tid] = v + (wid > 0 ? wsum[wid - 1] : 0);
    __syncthreads();

    const int total = csum[L_LEN - 1];

    // ---- binary search source row for each of the 48 frames ----
    if (tid < FRAMES) {
        int t  = t0 + tid;
        int id = -1;
        if (t < T && t < total) {
            int lo = 0, hi = L_LEN;
            while (lo < hi) {
                int mid = (lo + hi) >> 1;
                if (csum[mid] > t) hi = mid; else lo = mid + 1;
            }
            id = (lo < L_LEN) ? lo : (L_LEN - 1);
        }
        fidx[tid] = id;
    }
    __syncthreads();

    // ---- streaming copy: per-batch front-loaded ids, immediate STG.128 ----
    const int g = tid / 96;                // frame-group 0..2 (whole warps)
    const int c = tid - g * 96;            // channel chunk 0..95

    const float4* xv = (const float4*)(x + (size_t)n * L_LEN * 384);
    float4*       ov = (float4*)(out + ((size_t)n * T + t0) * 384) + c;
    const float4  z  = make_float4(0.f, 0.f, 0.f, 0.f);

    int    cur = -2;
    float4 val = z;
    const int fb = g * FPG;

    if (t0 + FRAMES <= T) {
        // full block: 2 batches of 8 frames, ids via LDS.128 pairs
        #pragma unroll
        for (int b = 0; b < FPG / 8; b++) {
            const int4 ia = ((const int4*)fidx)[g * (FPG / 4) + b * 2];
            const int4 ib = ((const int4*)fidx)[g * (FPG / 4) + b * 2 + 1];
            const int ids[8] = { ia.x, ia.y, ia.z, ia.w, ib.x, ib.y, ib.z, ib.w };

            float4* dst = ov + (size_t)(fb + b * 8) * 96;
            #pragma unroll
            for (int i = 0; i < 8; i++) {
                const int id = ids[i];
                if (id != cur) {           // warp-uniform
                    val = (id >= 0) ? __ldg(&xv[(size_t)id * 96 + c]) : z;
                    cur = id;
                }
                dst[(size_t)i * 96] = val; // immediate STG.128
            }
        }
    } else {
        // tail block (at most one per row)
        for (int i = 0; i < FPG; i++) {
            const int f = fb + i;
            if (t0 + f >= T) break;
            const int id = fidx[f];
            if (id != cur) {
                val = (id >= 0) ? __ldg(&xv[(size_t)id * 96 + c]) : z;
                cur = id;
            }
            ov[(size_t)f * 96] = val;
        }
    }
}

extern "C" void kernel_launch(void* const* d_in, const int* in_sizes, int n_in,
                              void* d_out, int out_size)
{
    const float* x   = (const float*)d_in[0];
    const int*   dur = (const int*)d_in[1];

    const int NL = in_sizes[1];            // N * L
    const int N  = NL / L_LEN;             // 64
    const int C  = in_sizes[0] / NL;       // 384 (layout assumes 384)

    const long long S    = (long long)out_size;
    const long long base = (long long)N * C;

    int T;
    int mel_is_i64 = 0;
    if (S % (base + 1) == 0) {
        T = (int)(S / (base + 1));         // case A: mel_pos as f32
    } else if (S % (base + 2) == 0) {
        T = (int)(S / (base + 2));         // case B: mel_pos as i64
        mel_is_i64 = 1;
    } else {
        T = (int)(S / base);               // fallback
    }

    float* out  = (float*)d_out;
    float* tail = out + (size_t)N * T * C;

    dim3 grid((T + FRAMES - 1) / FRAMES, N);
    lr_fused_kernel<<<grid, THREADS>>>(x, dur, out, tail, T, mel_is_i64);
}